// round 8
// baseline (speedup 1.0000x reference)
#include <cuda_runtime.h>
#include <math.h>

#define NPTS   16384
#define KNN    16
#define SEQ    8
#define NCELLS 32768      /* 32^3 morton cells */
#define NTILES 128        /* NPTS / TPT */
#define TPT    128        /* points per tile */
#define QPB    32         /* queries per knn block */
#define KNN_BLOCK 128
#define NBLK_LOSS 512

// ---------------- device scratch (no allocations allowed) ------------------
__device__ float4 g_sorted[NPTS];            // xyz + orig idx (bit-cast)
__device__ int    g_key[NPTS];
__device__ int    g_cnt[NCELLS];
__device__ int    g_cur[NCELLS];
__device__ float4 g_blo[NTILES];
__device__ float4 g_bhi[NTILES];
__device__ int    g_nn[NPTS * KNN];          // neighbors as SORTED positions
__device__ float4 g_fsorted[SEQ * NPTS];     // flow xyz + weight, sorted order
__device__ float  g_partials[NBLK_LOSS];
__device__ float  g_wsum;

// 5-bit -> every-3rd-bit spread for morton interleave
__device__ __forceinline__ unsigned mpart5(unsigned x) {
    x &= 31u;
    x = (x | (x << 8)) & 0x100Fu;
    x = (x | (x << 4)) & 0x10C3u;
    x = (x | (x << 2)) & 0x1249u;
    return x;
}

// ---------------------------------------------------------------------------
__global__ void zero_kernel() {
    int i = blockIdx.x * 256 + threadIdx.x;
    if (i < NCELLS) g_cnt[i] = 0;
}

__global__ void count_kernel(const float* __restrict__ pc) {
    int i = blockIdx.x * 256 + threadIdx.x;
    float x = pc[i * 3 + 0], y = pc[i * 3 + 1], z = pc[i * 3 + 2];
    int cx = min(31, max(0, (int)floorf((x + 5.0f) * 3.2f)));
    int cy = min(31, max(0, (int)floorf((y + 5.0f) * 3.2f)));
    int cz = min(31, max(0, (int)floorf((z + 5.0f) * 3.2f)));
    int key = (int)(mpart5(cx) | (mpart5(cy) << 1) | (mpart5(cz) << 2));
    g_key[i] = key;
    atomicAdd(&g_cnt[key], 1);
}

// single block, 1024 threads: exclusive scan of 32768 counts
__global__ void scan_kernel() {
    __shared__ int s[1024];
    int t = threadIdx.x;
    int base = t * 32;
    int loc[32];
    int sum = 0;
#pragma unroll
    for (int k = 0; k < 32; k++) { loc[k] = g_cnt[base + k]; sum += loc[k]; }
    s[t] = sum;
    __syncthreads();
    for (int off = 1; off < 1024; off <<= 1) {
        int v = (t >= off) ? s[t - off] : 0;
        __syncthreads();
        s[t] += v;
        __syncthreads();
    }
    int run = s[t] - sum;
#pragma unroll
    for (int k = 0; k < 32; k++) { g_cur[base + k] = run; run += loc[k]; }
}

__global__ void scatter_kernel(const float* __restrict__ pc) {
    int i = blockIdx.x * 256 + threadIdx.x;
    int pos = atomicAdd(&g_cur[g_key[i]], 1);
    g_sorted[pos] = make_float4(pc[i * 3 + 0], pc[i * 3 + 1], pc[i * 3 + 2],
                                __int_as_float(i));
}

// one warp per tile: shfl min/max reduce
__global__ void bbox_kernel() {
    const int tile = blockIdx.x;
    const int lane = threadIdx.x;
    float lx = 3e38f, ly = 3e38f, lz = 3e38f;
    float hx = -3e38f, hy = -3e38f, hz = -3e38f;
    const float4* p = g_sorted + tile * TPT;
#pragma unroll
    for (int j = 0; j < TPT / 32; j++) {
        float4 c = p[lane + j * 32];
        lx = fminf(lx, c.x); hx = fmaxf(hx, c.x);
        ly = fminf(ly, c.y); hy = fmaxf(hy, c.y);
        lz = fminf(lz, c.z); hz = fmaxf(hz, c.z);
    }
#pragma unroll
    for (int off = 16; off > 0; off >>= 1) {
        lx = fminf(lx, __shfl_xor_sync(0xFFFFFFFFu, lx, off));
        ly = fminf(ly, __shfl_xor_sync(0xFFFFFFFFu, ly, off));
        lz = fminf(lz, __shfl_xor_sync(0xFFFFFFFFu, lz, off));
        hx = fmaxf(hx, __shfl_xor_sync(0xFFFFFFFFu, hx, off));
        hy = fmaxf(hy, __shfl_xor_sync(0xFFFFFFFFu, hy, off));
        hz = fmaxf(hz, __shfl_xor_sync(0xFFFFFFFFu, hz, off));
    }
    if (lane == 0) {
        g_blo[tile] = make_float4(lx, ly, lz, 0.0f);
        g_bhi[tile] = make_float4(hx, hy, hz, 0.0f);
    }
}

// gather flow into sorted order, embed weight in .w
__global__ __launch_bounds__(256) void flowsort_kernel(const float* __restrict__ flow,
                                                       const float* __restrict__ w) {
    const int g = blockIdx.x * 256 + threadIdx.x;  // 0 .. SEQ*NPTS-1
    const int s = g / NPTS;
    const int p = g - s * NPTS;
    const int orig = __float_as_int(g_sorted[p].w);
    const float* f = flow + (size_t)s * NPTS * 3 + orig * 3;
    g_fsorted[g] = make_float4(f[0], f[1], f[2], w[orig]);
}

// ---------------------------------------------------------------------------
// Pruned kNN (R5 structure + RADIUS cap). Warp = 8 queries x 4 lanes.
// Expanding morton-tile sweep, register-cached threshold refreshed (2 shfls)
// only after a tile scan. KEY: threshold is CLAMPED to RADIUS^2 = 1.0 from
// the start: any neighbor with d2 > 1 is replaced by self downstream, so
// tiles with bbox-mind2 > 1 are provably irrelevant. This bounds the search
// for sparse tail queries (the worst-warp work that sets the wall clock).
// Lexicographic (d2, sorted-pos) => deterministic vs scatter atomic order.
// ---------------------------------------------------------------------------
__global__ __launch_bounds__(KNN_BLOCK) void knn_kernel() {
    __shared__ float4 slo[NTILES];
    __shared__ float4 shi[NTILES];
    __shared__ float md[QPB * 65];   // merge area, pitch 65
    __shared__ int   mi[QPB * 65];

    const int t    = threadIdx.x;
    const int lane = t & 31;
    const int part = lane & 3;                 // partition 0..3
    const int ql   = t >> 2;                   // local query 0..31
    const int gid  = blockIdx.x * QPB + ql;    // sorted query index
    const int tile0 = blockIdx.x >> 2;         // block spans quarter tile

    // preload bbox tables (4KB) — 128 threads load 2 float4 each
    if (t < NTILES) { slo[t] = g_blo[t]; shi[t] = g_bhi[t]; }
    __syncthreads();

    const float4 q = g_sorted[gid];

    float d[KNN];
    int   id[KNN];
#pragma unroll
    for (int k = 0; k < KNN; k++) { d[k] = 3.0e38f; id[k] = 0x7FFFFFFF; }

    float thr = 1.0f;   // RADIUS^2 cap: beyond this, neighbors map to self

    for (int s = 0; s < 2 * NTILES; s++) {
        int half = (s + 1) >> 1;
        int ti = (s & 1) ? (tile0 - half) : (tile0 + half);

        bool need = false;
        if ((unsigned)ti < NTILES) {
            float4 lo = slo[ti];
            float4 hi = shi[ti];
            float ddx = fmaxf(fmaxf(lo.x - q.x, q.x - hi.x), 0.0f);
            float ddy = fmaxf(fmaxf(lo.y - q.y, q.y - hi.y), 0.0f);
            float ddz = fmaxf(fmaxf(lo.z - q.z, q.z - hi.z), 0.0f);
            float mind2 = fmaf(ddx, ddx, fmaf(ddy, ddy, ddz * ddz));
            need = (mind2 <= thr);
        }

        if (__ballot_sync(0xFFFFFFFFu, need) == 0u) continue;

        if (need) {
            const float4* cp = g_sorted + ti * TPT;
            const int base = ti * TPT + part;
#pragma unroll 8
            for (int j = 0; j < TPT / 4; j++) {
                float4 c = cp[part + 4 * j];
                float dx = q.x - c.x;
                float dy = q.y - c.y;
                float dz = q.z - c.z;
                float d2 = fmaf(dx, dx, fmaf(dy, dy, dz * dz));
                int spos = base + 4 * j;
                if (d2 < d[KNN - 1] || (d2 == d[KNN - 1] && spos < id[KNN - 1])) {
                    bool placed = false;
#pragma unroll
                    for (int s2 = KNN - 1; s2 > 0; --s2) {
                        if (!placed) {
                            bool mv = (d[s2 - 1] > d2) ||
                                      (d[s2 - 1] == d2 && id[s2 - 1] > spos);
                            if (mv) { d[s2] = d[s2 - 1]; id[s2] = id[s2 - 1]; }
                            else    { d[s2] = d2; id[s2] = spos; placed = true; }
                        }
                    }
                    if (!placed) { d[0] = d2; id[0] = spos; }
                }
            }
        }

        // refresh cached threshold (only point where d[15] can change),
        // clamped at the RADIUS^2 cap
        float thr2 = d[KNN - 1];
        thr2 = fminf(thr2, __shfl_xor_sync(0xFFFFFFFFu, thr2, 1));
        thr2 = fminf(thr2, __shfl_xor_sync(0xFFFFFFFFu, thr2, 2));
        thr = fminf(thr2, 1.0f);
    }

    // ---- merge 4 partitions per query (single barrier) ----
    const int off = ql * 65 + part * KNN;
#pragma unroll
    for (int k = 0; k < KNN; k++) { md[off + k] = d[k]; mi[off + k] = id[k]; }
    __syncthreads();

    if (t < QPB) {
        const int boff = t * 65;
        float bd[KNN];
        int   bi[KNN];
#pragma unroll
        for (int k = 0; k < KNN; k++) { bd[k] = md[boff + k]; bi[k] = mi[boff + k]; }

        for (int p = 1; p < 4; p++) {
            const int po = boff + p * KNN;
            for (int k = 0; k < KNN; k++) {
                float v   = md[po + k];
                int   vid = mi[po + k];
                bool ins = (v < bd[KNN - 1]) ||
                           (v == bd[KNN - 1] && vid < bi[KNN - 1]);
                if (!ins) break;   // sorted sublist -> rest can't insert
                bool placed = false;
#pragma unroll
                for (int s2 = KNN - 1; s2 > 0; --s2) {
                    if (!placed) {
                        bool mv = (bd[s2 - 1] > v) ||
                                  (bd[s2 - 1] == v && bi[s2 - 1] > vid);
                        if (mv) { bd[s2] = bd[s2 - 1]; bi[s2] = bi[s2 - 1]; }
                        else    { bd[s2] = v; bi[s2] = vid; placed = true; }
                    }
                }
                if (!placed) { bd[0] = v; bi[0] = vid; }
            }
        }

        // radius filter: dist > 1 <=> d2 > 1 ; nearest (bd[0]=0) is self
        const int qq = blockIdx.x * QPB + t;   // sorted position
        const int self = bi[0];
#pragma unroll
        for (int k = 0; k < KNN; k++)
            g_nn[qq * KNN + k] = (bd[k] > 1.0f) ? self : bi[k];
    }
}

// ---------------------------------------------------------------------------
__global__ void wsum_kernel(const float* __restrict__ w) {
    __shared__ float red[256];
    float a = 0.0f;
    for (int i = threadIdx.x; i < NPTS; i += 256) a += w[i];
    red[threadIdx.x] = a;
    __syncthreads();
    for (int st = 128; st > 0; st >>= 1) {
        if (threadIdx.x < st) red[threadIdx.x] += red[threadIdx.x + st];
        __syncthreads();
    }
    if (threadIdx.x == 0) g_wsum = red[0];
}

// loss in sorted space: neighbor gathers are spatially local float4 loads
__global__ __launch_bounds__(256) void loss_kernel() {
    const int gid = blockIdx.x * 256 + threadIdx.x;  // 0 .. SEQ*NPTS-1
    const int s   = gid / NPTS;
    const int p   = gid - s * NPTS;
    const float4* f = g_fsorted + (size_t)s * NPTS;

    const float4 own = f[p];

    float acc = 0.0f;
#pragma unroll
    for (int k = 0; k < KNN; k++) {
        int j = g_nn[p * KNN + k];
        float4 c = f[j];
        float dx = own.x - c.x;
        float dy = own.y - c.y;
        float dz = own.z - c.z;
        float sq = dx * dx;
        sq = fmaf(dy, dy, sq);
        sq = fmaf(dz, dz, sq);
        acc += (sq > 0.0f) ? sqrtf(sq) : 0.0f;
    }
    float val = own.w * (acc * (1.0f / KNN));

    __shared__ float red[256];
    red[threadIdx.x] = val;
    __syncthreads();
    for (int st = 128; st > 0; st >>= 1) {
        if (threadIdx.x < st) red[threadIdx.x] += red[threadIdx.x + st];
        __syncthreads();
    }
    if (threadIdx.x == 0) g_partials[blockIdx.x] = red[0];
}

__global__ void final_kernel(float* __restrict__ out) {
    __shared__ float red[512];
    red[threadIdx.x] = g_partials[threadIdx.x];
    __syncthreads();
    for (int st = 256; st > 0; st >>= 1) {
        if (threadIdx.x < st) red[threadIdx.x] += red[threadIdx.x + st];
        __syncthreads();
    }
    if (threadIdx.x == 0) {
        float tot = red[0];
        float ws  = g_wsum;
        float ls  = (ws > 0.0f) ? (tot / ws) : tot;
        out[0] = ls * (1.0f / SEQ);
    }
}

// ---------------------------------------------------------------------------
extern "C" void kernel_launch(void* const* d_in, const int* in_sizes, int n_in,
                              void* d_out, int out_size) {
    const float* pc   = (const float*)d_in[0];  // (1, 16384, 3)
    const float* flow = (const float*)d_in[1];  // (8, 16384, 3)
    const float* w    = (const float*)d_in[2];  // (16384,)
    float* out = (float*)d_out;

    zero_kernel<<<NCELLS / 256, 256>>>();
    count_kernel<<<NPTS / 256, 256>>>(pc);
    scan_kernel<<<1, 1024>>>();
    scatter_kernel<<<NPTS / 256, 256>>>(pc);
    bbox_kernel<<<NTILES, 32>>>();
    flowsort_kernel<<<SEQ * NPTS / 256, 256>>>(flow, w);
    knn_kernel<<<NPTS / QPB, KNN_BLOCK>>>();
    wsum_kernel<<<1, 256>>>(w);
    loss_kernel<<<NBLK_LOSS, 256>>>();
    final_kernel<<<1, 512>>>(out);
}

// round 9
// speedup vs baseline: 2.0483x; 2.0483x over previous
#include <cuda_runtime.h>
#include <math.h>

#define NPTS   16384
#define KNN    16
#define SEQ    8
#define NCELLS 32768      /* 32^3 morton cells */
#define NTILES 128        /* NPTS / TPT */
#define TPT    128        /* points per tile */
#define QPB    64         /* queries per knn block */
#define NBLK_LOSS 512

// ---------------- device scratch (no allocations allowed) ------------------
__device__ float4 g_sorted[NPTS];            // xyz + orig idx (bit-cast)
__device__ int    g_key[NPTS];
__device__ int    g_cnt[NCELLS];
__device__ int    g_cur[NCELLS];
__device__ float4 g_blo[NTILES];
__device__ float4 g_bhi[NTILES];
__device__ int    g_nn[NPTS * KNN];          // neighbors as SORTED positions
__device__ float4 g_fsorted[SEQ * NPTS];     // flow xyz + weight, sorted order
__device__ float  g_partials[NBLK_LOSS];
__device__ float  g_wsum;

// 5-bit -> every-3rd-bit spread for morton interleave
__device__ __forceinline__ unsigned mpart5(unsigned x) {
    x &= 31u;
    x = (x | (x << 8)) & 0x100Fu;
    x = (x | (x << 4)) & 0x10C3u;
    x = (x | (x << 2)) & 0x1249u;
    return x;
}

// ---------------------------------------------------------------------------
__global__ void zero_kernel() {
    int i = blockIdx.x * 256 + threadIdx.x;
    if (i < NCELLS) g_cnt[i] = 0;
}

__global__ void count_kernel(const float* __restrict__ pc) {
    int i = blockIdx.x * 256 + threadIdx.x;
    float x = pc[i * 3 + 0], y = pc[i * 3 + 1], z = pc[i * 3 + 2];
    int cx = min(31, max(0, (int)floorf((x + 5.0f) * 3.2f)));
    int cy = min(31, max(0, (int)floorf((y + 5.0f) * 3.2f)));
    int cz = min(31, max(0, (int)floorf((z + 5.0f) * 3.2f)));
    int key = (int)(mpart5(cx) | (mpart5(cy) << 1) | (mpart5(cz) << 2));
    g_key[i] = key;
    atomicAdd(&g_cnt[key], 1);
}

// single block, 1024 threads: exclusive scan of 32768 counts
__global__ void scan_kernel() {
    __shared__ int s[1024];
    int t = threadIdx.x;
    int base = t * 32;
    int loc[32];
    int sum = 0;
#pragma unroll
    for (int k = 0; k < 32; k++) { loc[k] = g_cnt[base + k]; sum += loc[k]; }
    s[t] = sum;
    __syncthreads();
    for (int off = 1; off < 1024; off <<= 1) {
        int v = (t >= off) ? s[t - off] : 0;
        __syncthreads();
        s[t] += v;
        __syncthreads();
    }
    int run = s[t] - sum;
#pragma unroll
    for (int k = 0; k < 32; k++) { g_cur[base + k] = run; run += loc[k]; }
}

__global__ void scatter_kernel(const float* __restrict__ pc) {
    int i = blockIdx.x * 256 + threadIdx.x;
    int pos = atomicAdd(&g_cur[g_key[i]], 1);
    g_sorted[pos] = make_float4(pc[i * 3 + 0], pc[i * 3 + 1], pc[i * 3 + 2],
                                __int_as_float(i));
}

// one warp per tile: shfl min/max reduce
__global__ void bbox_kernel() {
    const int tile = blockIdx.x;
    const int lane = threadIdx.x;
    float lx = 3e38f, ly = 3e38f, lz = 3e38f;
    float hx = -3e38f, hy = -3e38f, hz = -3e38f;
    const float4* p = g_sorted + tile * TPT;
#pragma unroll
    for (int j = 0; j < TPT / 32; j++) {
        float4 c = p[lane + j * 32];
        lx = fminf(lx, c.x); hx = fmaxf(hx, c.x);
        ly = fminf(ly, c.y); hy = fmaxf(hy, c.y);
        lz = fminf(lz, c.z); hz = fmaxf(hz, c.z);
    }
#pragma unroll
    for (int off = 16; off > 0; off >>= 1) {
        lx = fminf(lx, __shfl_xor_sync(0xFFFFFFFFu, lx, off));
        ly = fminf(ly, __shfl_xor_sync(0xFFFFFFFFu, ly, off));
        lz = fminf(lz, __shfl_xor_sync(0xFFFFFFFFu, lz, off));
        hx = fmaxf(hx, __shfl_xor_sync(0xFFFFFFFFu, hx, off));
        hy = fmaxf(hy, __shfl_xor_sync(0xFFFFFFFFu, hy, off));
        hz = fmaxf(hz, __shfl_xor_sync(0xFFFFFFFFu, hz, off));
    }
    if (lane == 0) {
        g_blo[tile] = make_float4(lx, ly, lz, 0.0f);
        g_bhi[tile] = make_float4(hx, hy, hz, 0.0f);
    }
}

// gather flow into sorted order, embed weight in .w
__global__ __launch_bounds__(256) void flowsort_kernel(const float* __restrict__ flow,
                                                       const float* __restrict__ w) {
    const int g = blockIdx.x * 256 + threadIdx.x;  // 0 .. SEQ*NPTS-1
    const int s = g / NPTS;
    const int p = g - s * NPTS;
    const int orig = __float_as_int(g_sorted[p].w);
    const float* f = flow + (size_t)s * NPTS * 3 + orig * 3;
    g_fsorted[g] = make_float4(f[0], f[1], f[2], w[orig]);
}

// ---------------------------------------------------------------------------
// Pruned kNN (exact R5 structure + RADIUS^2 threshold cap — the ONLY change).
// Warp = 8 queries x 4 partition lanes. Expanding morton-tile sweep; warp
// ballot skips tiles nobody needs; pruning threshold cached in a register and
// refreshed (2 shfls) only after a tile scan. Threshold clamped to
// RADIUS^2 = 1.0: any neighbor with d2 > 1 maps to self downstream, so tiles
// with bbox-mind2 > 1 are irrelevant — this bounds the sparse tail queries
// whose loose thresholds otherwise set the worst-warp wall clock.
// Lexicographic (d2, sorted-pos) => deterministic vs scatter atomic order.
// ---------------------------------------------------------------------------
__global__ __launch_bounds__(256) void knn_kernel() {
    __shared__ float md[QPB * 65];   // merge area, pitch 65
    __shared__ int   mi[QPB * 65];

    const int t    = threadIdx.x;
    const int lane = t & 31;
    const int part = lane & 3;                 // partition 0..3
    const int ql   = t >> 2;                   // local query 0..63
    const int gid  = blockIdx.x * QPB + ql;    // sorted query index
    const int tile0 = blockIdx.x >> 1;         // block spans half a tile

    const float4 q = g_sorted[gid];

    float d[KNN];
    int   id[KNN];
#pragma unroll
    for (int k = 0; k < KNN; k++) { d[k] = 3.0e38f; id[k] = 0x7FFFFFFF; }

    float thr = 1.0f;   // RADIUS^2 cap: beyond this, neighbors map to self

    for (int s = 0; s < 2 * NTILES; s++) {
        int half = (s + 1) >> 1;
        int ti = (s & 1) ? (tile0 - half) : (tile0 + half);

        bool need = false;
        if ((unsigned)ti < NTILES) {
            float4 lo = g_blo[ti];
            float4 hi = g_bhi[ti];
            float ddx = fmaxf(fmaxf(lo.x - q.x, q.x - hi.x), 0.0f);
            float ddy = fmaxf(fmaxf(lo.y - q.y, q.y - hi.y), 0.0f);
            float ddz = fmaxf(fmaxf(lo.z - q.z, q.z - hi.z), 0.0f);
            float mind2 = fmaf(ddx, ddx, fmaf(ddy, ddy, ddz * ddz));
            need = (mind2 <= thr);
        }

        if (__ballot_sync(0xFFFFFFFFu, need) == 0u) continue;

        if (need) {
            const float4* cp = g_sorted + ti * TPT;
            const int base = ti * TPT + part;
#pragma unroll 4
            for (int j = 0; j < TPT / 4; j++) {
                float4 c = cp[part + 4 * j];
                float dx = q.x - c.x;
                float dy = q.y - c.y;
                float dz = q.z - c.z;
                float d2 = fmaf(dx, dx, fmaf(dy, dy, dz * dz));
                int spos = base + 4 * j;
                if (d2 < d[KNN - 1] || (d2 == d[KNN - 1] && spos < id[KNN - 1])) {
                    bool placed = false;
#pragma unroll
                    for (int s2 = KNN - 1; s2 > 0; --s2) {
                        if (!placed) {
                            bool mv = (d[s2 - 1] > d2) ||
                                      (d[s2 - 1] == d2 && id[s2 - 1] > spos);
                            if (mv) { d[s2] = d[s2 - 1]; id[s2] = id[s2 - 1]; }
                            else    { d[s2] = d2; id[s2] = spos; placed = true; }
                        }
                    }
                    if (!placed) { d[0] = d2; id[0] = spos; }
                }
            }
        }

        // refresh cached threshold (only point where d[15] can have changed),
        // clamped at the RADIUS^2 cap
        float thr2 = d[KNN - 1];
        thr2 = fminf(thr2, __shfl_xor_sync(0xFFFFFFFFu, thr2, 1));
        thr2 = fminf(thr2, __shfl_xor_sync(0xFFFFFFFFu, thr2, 2));
        thr = fminf(thr2, 1.0f);
    }

    // ---- merge 4 partitions per query (single barrier) ----
    const int off = ql * 65 + part * KNN;
#pragma unroll
    for (int k = 0; k < KNN; k++) { md[off + k] = d[k]; mi[off + k] = id[k]; }
    __syncthreads();

    if (t < QPB) {
        const int boff = t * 65;
        float bd[KNN];
        int   bi[KNN];
#pragma unroll
        for (int k = 0; k < KNN; k++) { bd[k] = md[boff + k]; bi[k] = mi[boff + k]; }

        for (int p = 1; p < 4; p++) {
            const int po = boff + p * KNN;
            for (int k = 0; k < KNN; k++) {
                float v   = md[po + k];
                int   vid = mi[po + k];
                bool ins = (v < bd[KNN - 1]) ||
                           (v == bd[KNN - 1] && vid < bi[KNN - 1]);
                if (!ins) break;   // sorted sublist -> rest can't insert
                bool placed = false;
#pragma unroll
                for (int s2 = KNN - 1; s2 > 0; --s2) {
                    if (!placed) {
                        bool mv = (bd[s2 - 1] > v) ||
                                  (bd[s2 - 1] == v && bi[s2 - 1] > vid);
                        if (mv) { bd[s2] = bd[s2 - 1]; bi[s2] = bi[s2 - 1]; }
                        else    { bd[s2] = v; bi[s2] = vid; placed = true; }
                    }
                }
                if (!placed) { bd[0] = v; bi[0] = vid; }
            }
        }

        // radius filter: dist > 1 <=> d2 > 1 ; nearest (bd[0]=0) is self
        const int qq = blockIdx.x * QPB + t;   // sorted position
        const int self = bi[0];
#pragma unroll
        for (int k = 0; k < KNN; k++)
            g_nn[qq * KNN + k] = (bd[k] > 1.0f) ? self : bi[k];
    }
}

// ---------------------------------------------------------------------------
__global__ void wsum_kernel(const float* __restrict__ w) {
    __shared__ float red[256];
    float a = 0.0f;
    for (int i = threadIdx.x; i < NPTS; i += 256) a += w[i];
    red[threadIdx.x] = a;
    __syncthreads();
    for (int st = 128; st > 0; st >>= 1) {
        if (threadIdx.x < st) red[threadIdx.x] += red[threadIdx.x + st];
        __syncthreads();
    }
    if (threadIdx.x == 0) g_wsum = red[0];
}

// loss in sorted space: neighbor gathers are spatially local float4 loads
__global__ __launch_bounds__(256) void loss_kernel() {
    const int gid = blockIdx.x * 256 + threadIdx.x;  // 0 .. SEQ*NPTS-1
    const int s   = gid / NPTS;
    const int p   = gid - s * NPTS;
    const float4* f = g_fsorted + (size_t)s * NPTS;

    const float4 own = f[p];

    float acc = 0.0f;
#pragma unroll
    for (int k = 0; k < KNN; k++) {
        int j = g_nn[p * KNN + k];
        float4 c = f[j];
        float dx = own.x - c.x;
        float dy = own.y - c.y;
        float dz = own.z - c.z;
        float sq = dx * dx;
        sq = fmaf(dy, dy, sq);
        sq = fmaf(dz, dz, sq);
        acc += (sq > 0.0f) ? sqrtf(sq) : 0.0f;
    }
    float val = own.w * (acc * (1.0f / KNN));

    __shared__ float red[256];
    red[threadIdx.x] = val;
    __syncthreads();
    for (int st = 128; st > 0; st >>= 1) {
        if (threadIdx.x < st) red[threadIdx.x] += red[threadIdx.x + st];
        __syncthreads();
    }
    if (threadIdx.x == 0) g_partials[blockIdx.x] = red[0];
}

__global__ void final_kernel(float* __restrict__ out) {
    __shared__ float red[512];
    red[threadIdx.x] = g_partials[threadIdx.x];
    __syncthreads();
    for (int st = 256; st > 0; st >>= 1) {
        if (threadIdx.x < st) red[threadIdx.x] += red[threadIdx.x + st];
        __syncthreads();
    }
    if (threadIdx.x == 0) {
        float tot = red[0];
        float ws  = g_wsum;
        float ls  = (ws > 0.0f) ? (tot / ws) : tot;
        out[0] = ls * (1.0f / SEQ);
    }
}

// ---------------------------------------------------------------------------
extern "C" void kernel_launch(void* const* d_in, const int* in_sizes, int n_in,
                              void* d_out, int out_size) {
    const float* pc   = (const float*)d_in[0];  // (1, 16384, 3)
    const float* flow = (const float*)d_in[1];  // (8, 16384, 3)
    const float* w    = (const float*)d_in[2];  // (16384,)
    float* out = (float*)d_out;

    zero_kernel<<<NCELLS / 256, 256>>>();
    count_kernel<<<NPTS / 256, 256>>>(pc);
    scan_kernel<<<1, 1024>>>();
    scatter_kernel<<<NPTS / 256, 256>>>(pc);
    bbox_kernel<<<NTILES, 32>>>();
    flowsort_kernel<<<SEQ * NPTS / 256, 256>>>(flow, w);
    knn_kernel<<<NPTS / QPB, 256>>>();
    wsum_kernel<<<1, 256>>>(w);
    loss_kernel<<<NBLK_LOSS, 256>>>();
    final_kernel<<<1, 512>>>(out);
}

// round 11
// speedup vs baseline: 2.1081x; 1.0292x over previous
#include <cuda_runtime.h>
#include <math.h>

#define NPTS   16384
#define KNN    16
#define SEQ    8
#define NCELLS 32768      /* 32^3 morton cells */
#define NTILES 256        /* NPTS / TPT */
#define TPT    64         /* points per tile */
#define QPB    64         /* queries per knn block */
#define NBLK_LOSS 512

// ---------------- device scratch (no allocations allowed) ------------------
__device__ float4 g_sorted[NPTS];            // xyz + orig idx (bit-cast)
__device__ int    g_key[NPTS];
__device__ int    g_cnt[NCELLS];
__device__ int    g_cur[NCELLS];
__device__ float4 g_blo[NTILES];
__device__ float4 g_bhi[NTILES];
__device__ int    g_nn[NPTS * KNN];          // neighbors as SORTED positions
__device__ float4 g_fsorted[SEQ * NPTS];     // flow xyz + weight, sorted order
__device__ float  g_partials[NBLK_LOSS];
__device__ float  g_wsum;

// 5-bit -> every-3rd-bit spread for morton interleave
__device__ __forceinline__ unsigned mpart5(unsigned x) {
    x &= 31u;
    x = (x | (x << 8)) & 0x100Fu;
    x = (x | (x << 4)) & 0x10C3u;
    x = (x | (x << 2)) & 0x1249u;
    return x;
}

// ---------------------------------------------------------------------------
__global__ void zero_kernel() {
    int i = blockIdx.x * 256 + threadIdx.x;
    if (i < NCELLS) g_cnt[i] = 0;
}

__global__ void count_kernel(const float* __restrict__ pc) {
    int i = blockIdx.x * 256 + threadIdx.x;
    float x = pc[i * 3 + 0], y = pc[i * 3 + 1], z = pc[i * 3 + 2];
    int cx = min(31, max(0, (int)floorf((x + 5.0f) * 3.2f)));
    int cy = min(31, max(0, (int)floorf((y + 5.0f) * 3.2f)));
    int cz = min(31, max(0, (int)floorf((z + 5.0f) * 3.2f)));
    int key = (int)(mpart5(cx) | (mpart5(cy) << 1) | (mpart5(cz) << 2));
    g_key[i] = key;
    atomicAdd(&g_cnt[key], 1);
}

// single block, 1024 threads: exclusive scan of 32768 counts
__global__ void scan_kernel() {
    __shared__ int s[1024];
    int t = threadIdx.x;
    int base = t * 32;
    int loc[32];
    int sum = 0;
#pragma unroll
    for (int k = 0; k < 32; k++) { loc[k] = g_cnt[base + k]; sum += loc[k]; }
    s[t] = sum;
    __syncthreads();
    for (int off = 1; off < 1024; off <<= 1) {
        int v = (t >= off) ? s[t - off] : 0;
        __syncthreads();
        s[t] += v;
        __syncthreads();
    }
    int run = s[t] - sum;
#pragma unroll
    for (int k = 0; k < 32; k++) { g_cur[base + k] = run; run += loc[k]; }
}

__global__ void scatter_kernel(const float* __restrict__ pc) {
    int i = blockIdx.x * 256 + threadIdx.x;
    int pos = atomicAdd(&g_cur[g_key[i]], 1);
    g_sorted[pos] = make_float4(pc[i * 3 + 0], pc[i * 3 + 1], pc[i * 3 + 2],
                                __int_as_float(i));
}

// one warp per tile: shfl min/max reduce
__global__ void bbox_kernel() {
    const int tile = blockIdx.x;
    const int lane = threadIdx.x;
    float lx = 3e38f, ly = 3e38f, lz = 3e38f;
    float hx = -3e38f, hy = -3e38f, hz = -3e38f;
    const float4* p = g_sorted + tile * TPT;
#pragma unroll
    for (int j = 0; j < TPT / 32; j++) {
        float4 c = p[lane + j * 32];
        lx = fminf(lx, c.x); hx = fmaxf(hx, c.x);
        ly = fminf(ly, c.y); hy = fmaxf(hy, c.y);
        lz = fminf(lz, c.z); hz = fmaxf(hz, c.z);
    }
#pragma unroll
    for (int off = 16; off > 0; off >>= 1) {
        lx = fminf(lx, __shfl_xor_sync(0xFFFFFFFFu, lx, off));
        ly = fminf(ly, __shfl_xor_sync(0xFFFFFFFFu, ly, off));
        lz = fminf(lz, __shfl_xor_sync(0xFFFFFFFFu, lz, off));
        hx = fmaxf(hx, __shfl_xor_sync(0xFFFFFFFFu, hx, off));
        hy = fmaxf(hy, __shfl_xor_sync(0xFFFFFFFFu, hy, off));
        hz = fmaxf(hz, __shfl_xor_sync(0xFFFFFFFFu, hz, off));
    }
    if (lane == 0) {
        g_blo[tile] = make_float4(lx, ly, lz, 0.0f);
        g_bhi[tile] = make_float4(hx, hy, hz, 0.0f);
    }
}

// gather flow into sorted order, embed weight in .w
__global__ __launch_bounds__(256) void flowsort_kernel(const float* __restrict__ flow,
                                                       const float* __restrict__ w) {
    const int g = blockIdx.x * 256 + threadIdx.x;  // 0 .. SEQ*NPTS-1
    const int s = g / NPTS;
    const int p = g - s * NPTS;
    const int orig = __float_as_int(g_sorted[p].w);
    const float* f = flow + (size_t)s * NPTS * 3 + orig * 3;
    g_fsorted[g] = make_float4(f[0], f[1], f[2], w[orig]);
}

// ---------------------------------------------------------------------------
// Pruned kNN (R5 structure; tile granularity 128 -> 64 is this round's single
// change). Warp = 8 queries x 4 partition lanes. Expanding morton-tile sweep;
// warp ballot skips tiles nobody needs; pruning threshold cached in a
// register, refreshed (2 shfls) only after a tile scan, clamped at
// RADIUS^2 = 1.0 (neighbors with d2 > 1 map to self downstream). Halving the
// tile size doubles bbox-prune resolution, cutting scanned candidates ~40%.
// Lexicographic (d2, sorted-pos) => deterministic vs scatter atomic order.
// ---------------------------------------------------------------------------
__global__ __launch_bounds__(256) void knn_kernel() {
    __shared__ float md[QPB * 65];   // merge area, pitch 65
    __shared__ int   mi[QPB * 65];

    const int t    = threadIdx.x;
    const int lane = t & 31;
    const int part = lane & 3;                 // partition 0..3
    const int ql   = t >> 2;                   // local query 0..63
    const int gid  = blockIdx.x * QPB + ql;    // sorted query index
    const int tile0 = blockIdx.x;              // block spans exactly one tile

    const float4 q = g_sorted[gid];

    float d[KNN];
    int   id[KNN];
#pragma unroll
    for (int k = 0; k < KNN; k++) { d[k] = 3.0e38f; id[k] = 0x7FFFFFFF; }

    float thr = 1.0f;   // RADIUS^2 cap: beyond this, neighbors map to self

    for (int s = 0; s < 2 * NTILES; s++) {
        int half = (s + 1) >> 1;
        int ti = (s & 1) ? (tile0 - half) : (tile0 + half);

        bool need = false;
        if ((unsigned)ti < NTILES) {
            float4 lo = g_blo[ti];
            float4 hi = g_bhi[ti];
            float ddx = fmaxf(fmaxf(lo.x - q.x, q.x - hi.x), 0.0f);
            float ddy = fmaxf(fmaxf(lo.y - q.y, q.y - hi.y), 0.0f);
            float ddz = fmaxf(fmaxf(lo.z - q.z, q.z - hi.z), 0.0f);
            float mind2 = fmaf(ddx, ddx, fmaf(ddy, ddy, ddz * ddz));
            need = (mind2 <= thr);
        }

        if (__ballot_sync(0xFFFFFFFFu, need) == 0u) continue;

        if (need) {
            const float4* cp = g_sorted + ti * TPT;
            const int base = ti * TPT + part;
#pragma unroll 4
            for (int j = 0; j < TPT / 4; j++) {
                float4 c = cp[part + 4 * j];
                float dx = q.x - c.x;
                float dy = q.y - c.y;
                float dz = q.z - c.z;
                float d2 = fmaf(dx, dx, fmaf(dy, dy, dz * dz));
                int spos = base + 4 * j;
                if (d2 < d[KNN - 1] || (d2 == d[KNN - 1] && spos < id[KNN - 1])) {
                    bool placed = false;
#pragma unroll
                    for (int s2 = KNN - 1; s2 > 0; --s2) {
                        if (!placed) {
                            bool mv = (d[s2 - 1] > d2) ||
                                      (d[s2 - 1] == d2 && id[s2 - 1] > spos);
                            if (mv) { d[s2] = d[s2 - 1]; id[s2] = id[s2 - 1]; }
                            else    { d[s2] = d2; id[s2] = spos; placed = true; }
                        }
                    }
                    if (!placed) { d[0] = d2; id[0] = spos; }
                }
            }
        }

        // refresh cached threshold (only point where d[15] can have changed),
        // clamped at the RADIUS^2 cap
        float thr2 = d[KNN - 1];
        thr2 = fminf(thr2, __shfl_xor_sync(0xFFFFFFFFu, thr2, 1));
        thr2 = fminf(thr2, __shfl_xor_sync(0xFFFFFFFFu, thr2, 2));
        thr = fminf(thr2, 1.0f);
    }

    // ---- merge 4 partitions per query (single barrier) ----
    const int off = ql * 65 + part * KNN;
#pragma unroll
    for (int k = 0; k < KNN; k++) { md[off + k] = d[k]; mi[off + k] = id[k]; }
    __syncthreads();

    if (t < QPB) {
        const int boff = t * 65;
        float bd[KNN];
        int   bi[KNN];
#pragma unroll
        for (int k = 0; k < KNN; k++) { bd[k] = md[boff + k]; bi[k] = mi[boff + k]; }

        for (int p = 1; p < 4; p++) {
            const int po = boff + p * KNN;
            for (int k = 0; k < KNN; k++) {
                float v   = md[po + k];
                int   vid = mi[po + k];
                bool ins = (v < bd[KNN - 1]) ||
                           (v == bd[KNN - 1] && vid < bi[KNN - 1]);
                if (!ins) break;   // sorted sublist -> rest can't insert
                bool placed = false;
#pragma unroll
                for (int s2 = KNN - 1; s2 > 0; --s2) {
                    if (!placed) {
                        bool mv = (bd[s2 - 1] > v) ||
                                  (bd[s2 - 1] == v && bi[s2 - 1] > vid);
                        if (mv) { bd[s2] = bd[s2 - 1]; bi[s2] = bi[s2 - 1]; }
                        else    { bd[s2] = v; bi[s2] = vid; placed = true; }
                    }
                }
                if (!placed) { bd[0] = v; bi[0] = vid; }
            }
        }

        // radius filter: dist > 1 <=> d2 > 1 ; nearest (bd[0]=0) is self
        const int qq = blockIdx.x * QPB + t;   // sorted position
        const int self = bi[0];
#pragma unroll
        for (int k = 0; k < KNN; k++)
            g_nn[qq * KNN + k] = (bd[k] > 1.0f) ? self : bi[k];
    }
}

// ---------------------------------------------------------------------------
__global__ void wsum_kernel(const float* __restrict__ w) {
    __shared__ float red[256];
    float a = 0.0f;
    for (int i = threadIdx.x; i < NPTS; i += 256) a += w[i];
    red[threadIdx.x] = a;
    __syncthreads();
    for (int st = 128; st > 0; st >>= 1) {
        if (threadIdx.x < st) red[threadIdx.x] += red[threadIdx.x + st];
        __syncthreads();
    }
    if (threadIdx.x == 0) g_wsum = red[0];
}

// loss in sorted space: neighbor gathers are spatially local float4 loads
__global__ __launch_bounds__(256) void loss_kernel() {
    const int gid = blockIdx.x * 256 + threadIdx.x;  // 0 .. SEQ*NPTS-1
    const int s   = gid / NPTS;
    const int p   = gid - s * NPTS;
    const float4* f = g_fsorted + (size_t)s * NPTS;

    const float4 own = f[p];

    // vectorized neighbor-index loads: 4 x int4
    const int4* nn4 = (const int4*)(g_nn + p * KNN);
    float acc = 0.0f;
#pragma unroll
    for (int v = 0; v < 4; v++) {
        int4 j4 = nn4[v];
#pragma unroll
        for (int u = 0; u < 4; u++) {
            int j = (u == 0) ? j4.x : (u == 1) ? j4.y : (u == 2) ? j4.z : j4.w;
            float4 c = f[j];
            float dx = own.x - c.x;
            float dy = own.y - c.y;
            float dz = own.z - c.z;
            float sq = dx * dx;
            sq = fmaf(dy, dy, sq);
            sq = fmaf(dz, dz, sq);
            acc += (sq > 0.0f) ? sqrtf(sq) : 0.0f;
        }
    }
    float val = own.w * (acc * (1.0f / KNN));

    __shared__ float red[256];
    red[threadIdx.x] = val;
    __syncthreads();
    for (int st = 128; st > 0; st >>= 1) {
        if (threadIdx.x < st) red[threadIdx.x] += red[threadIdx.x + st];
        __syncthreads();
    }
    if (threadIdx.x == 0) g_partials[blockIdx.x] = red[0];
}

__global__ void final_kernel(float* __restrict__ out) {
    __shared__ float red[512];
    red[threadIdx.x] = g_partials[threadIdx.x];
    __syncthreads();
    for (int st = 256; st > 0; st >>= 1) {
        if (threadIdx.x < st) red[threadIdx.x] += red[threadIdx.x + st];
        __syncthreads();
    }
    if (threadIdx.x == 0) {
        float tot = red[0];
        float ws  = g_wsum;
        float ls  = (ws > 0.0f) ? (tot / ws) : tot;
        out[0] = ls * (1.0f / SEQ);
    }
}

// ---------------------------------------------------------------------------
extern "C" void kernel_launch(void* const* d_in, const int* in_sizes, int n_in,
                              void* d_out, int out_size) {
    const float* pc   = (const float*)d_in[0];  // (1, 16384, 3)
    const float* flow = (const float*)d_in[1];  // (8, 16384, 3)
    const float* w    = (const float*)d_in[2];  // (16384,)
    float* out = (float*)d_out;

    zero_kernel<<<NCELLS / 256, 256>>>();
    count_kernel<<<NPTS / 256, 256>>>(pc);
    scan_kernel<<<1, 1024>>>();
    scatter_kernel<<<NPTS / 256, 256>>>(pc);
    bbox_kernel<<<NTILES, 32>>>();
    flowsort_kernel<<<SEQ * NPTS / 256, 256>>>(flow, w);
    knn_kernel<<<NPTS / QPB, 256>>>();
    wsum_kernel<<<1, 256>>>(w);
    loss_kernel<<<NBLK_LOSS, 256>>>();
    final_kernel<<<1, 512>>>(out);
}